// round 15
// baseline (speedup 1.0000x reference)
#include <cuda_runtime.h>
#include <cuda_fp16.h>
#include <cstdint>

#define HW   16384
#define CCH  256
#define EPSF 1e-8f

// ---------------- scratch (no allocations allowed; static zero-init is the
// call-0 state, and the last k_loss block restores it for graph replays) ----
__device__ float              g_inv_nb[HW];
__device__ float              g_bn[HW];
__device__ float              g_an[HW];
__device__ unsigned long long g_best[HW];       // stays 0 at call boundaries
__device__ unsigned long long g_sum;
__device__ unsigned int       g_cnt;
__device__ unsigned int       g_flag[1024];     // cvt strip-ready flags [z*512+strip]
__device__ unsigned int       g_done[64];       // gemm tiles finished per bm-group
__device__ __half             g_ah[HW * CCH];   // fp16 a, [p][c] K-major, 8MB
__device__ __half             g_bh[HW * CCH];   // fp16 b * inv_nb[q], [q][c], 8MB

// ---------------- helpers ----------------
__device__ __forceinline__ uint32_t smem_to_u32(const void* p) {
    uint32_t a;
    asm("{ .reg .u64 t; cvta.to.shared.u64 t, %1; cvt.u32.u64 %0, t; }" : "=r"(a) : "l"(p));
    return a;
}
// .cg: bypass L1 (stage data is never re-read through L1; avoids pollution)
__device__ __forceinline__ void cp16(uint32_t dst, const void* src) {
    asm volatile("cp.async.cg.shared.global [%0], [%1], 16;" :: "r"(dst), "l"(src) : "memory");
}
__device__ __forceinline__ void mma_f16acc(uint32_t* d, const uint32_t* a, const uint32_t* b) {
    asm volatile(
        "mma.sync.aligned.m16n8k16.row.col.f16.f16.f16.f16 "
        "{%0,%1}, {%2,%3,%4,%5}, {%6,%7}, {%0,%1};"
        : "+r"(d[0]), "+r"(d[1])
        : "r"(a[0]), "r"(a[1]), "r"(a[2]), "r"(a[3]), "r"(b[0]), "r"(b[1]));
}
__device__ __forceinline__ void ldsm4(uint32_t* r, uint32_t addr) {
    asm volatile("ldmatrix.sync.aligned.m8n8.x4.shared.b16 {%0,%1,%2,%3}, [%4];"
                 : "=r"(r[0]), "=r"(r[1]), "=r"(r[2]), "=r"(r[3]) : "r"(addr));
}

// smem: 2 stage buffers of (A 32KB + B 16KB), K=64 stages, 128B rows
static constexpr int BUF_BYTES  = 49152;
static constexpr int SMEM_BYTES = 2 * BUF_BYTES;   // 98304

// ---------------- kernel 0: fused transpose->fp16 + exact norms + strip flags ----------------
// b is stored PRE-SCALED by inv_nb so the GEMM epilogue is a pure argmax.
__global__ void k_cvt(const float* __restrict__ a, const float* __restrict__ b) {
    __shared__ float t[32][257];   // [pixel][channel]
    __shared__ float ps[8][33];
    __shared__ float scl[32];
    const int z = blockIdx.y;
    const float* src = z ? b : a;
    __half*      dst = z ? g_bh : g_ah;
    const int p0 = blockIdx.x * 32;
    const int tx = threadIdx.x, ty = threadIdx.y;   // 32 x 8

    if (tx == 0 && ty == 0) cudaTriggerProgrammaticLaunchCompletion();

    float ss = 0.f;
    #pragma unroll
    for (int i = 0; i < 32; ++i) {
        int c = ty + i * 8;
        float v = src[(size_t)c * HW + p0 + tx];
        t[tx][c] = v;
        ss = fmaf(v, v, ss);
    }
    ps[ty][tx] = ss;
    __syncthreads();

    if (ty == 0) {
        float s = 0.f;
        #pragma unroll
        for (int j = 0; j < 8; ++j) s += ps[j][tx];
        int p = p0 + tx;
        if (z) {
            float inv = 1.f / (sqrtf(s + EPSF) + EPSF);
            g_inv_nb[p] = inv;
            g_bn[p]     = sqrtf(s);
            scl[tx]     = inv;
        } else {
            g_an[p] = sqrtf(s);
            scl[tx] = 1.f;
        }
    }
    __syncthreads();

    #pragma unroll
    for (int pp = 0; pp < 4; ++pp) {
        int px = ty * 4 + pp;
        int c0 = tx * 8;
        float sc = scl[px];
        uint32_t w[4];
        #pragma unroll
        for (int j = 0; j < 4; ++j) {
            __half2 h = __floats2half2_rn(t[px][c0 + 2 * j] * sc, t[px][c0 + 2 * j + 1] * sc);
            w[j] = *(uint32_t*)&h;
        }
        *(uint4*)(dst + (size_t)(p0 + px) * CCH + c0) = make_uint4(w[0], w[1], w[2], w[3]);
    }

    // release this strip for the overlapped GEMM
    __threadfence();
    __syncthreads();
    if (tx == 0 && ty == 0)
        atomicExch(&g_flag[z * 512 + blockIdx.x], 1u);
}

// ---------------- kernel 1: fp16 GEMM, CTA 256x128, warp tile 128x64, fp16 acc ----------------
__device__ __forceinline__ void load_stage(uint32_t smb, int bufOff,
                                           int bm, int bn, int s, int tid) {
    // A: 256 rows x 64 K fp16 (128B rows), 2048 16B-chunks
    #pragma unroll
    for (int i = 0; i < 16; ++i) {
        int idx = tid + i * 128;
        int row = idx >> 3, seg = idx & 7;
        uint32_t d = smb + bufOff + row * 128 + ((seg ^ (row & 7)) << 4);
        cp16(d, g_ah + (size_t)(bm + row) * CCH + s * 64 + seg * 8);
    }
    // B: 128 rows x 64 K fp16, 1024 chunks
    #pragma unroll
    for (int i = 0; i < 8; ++i) {
        int idx = tid + i * 128;
        int row = idx >> 3, seg = idx & 7;
        uint32_t d = smb + bufOff + 32768 + row * 128 + ((seg ^ (row & 7)) << 4);
        cp16(d, g_bh + (size_t)(bn + row) * CCH + s * 64 + seg * 8);
    }
}

__global__ void __launch_bounds__(128, 2)
k_gemm() {
    extern __shared__ __align__(1024) char sm[];
    const uint32_t smb = smem_to_u32(sm);
    const int tid  = threadIdx.x;
    const int lane = tid & 31;
    const int wid  = tid >> 5;    // 0..3
    const int wm   = wid & 1;     // 2 warps along M (128 rows each)
    const int wn   = wid >> 1;    // 2 warps along N (64 cols each)
    const int g    = lane >> 2;
    const int tig  = lane & 3;
    const int t8   = lane >> 3;
    const int jr   = lane & 7;

    const int bm = blockIdx.x * 256;   // M fast
    const int bn = blockIdx.y * 128;

    // PDL: release our own dependent (k_loss) gate, then wait for the cvt
    // strips this CTA actually consumes.
    if (tid == 0) {
        cudaTriggerProgrammaticLaunchCompletion();
        const int a0 = blockIdx.x * 8;          // 8 A strips
        const int b0 = 512 + blockIdx.y * 4;    // 4 B strips
        #pragma unroll
        for (int i = 0; i < 8; ++i)
            while (((volatile unsigned int*)g_flag)[a0 + i] == 0u) __nanosleep(64);
        #pragma unroll
        for (int i = 0; i < 4; ++i)
            while (((volatile unsigned int*)g_flag)[b0 + i] == 0u) __nanosleep(64);
        __threadfence();
    }
    __syncthreads();

    // ldmatrix per-lane address invariants
    const uint32_t aRow = (uint32_t)((wm * 128 + (t8 & 1) * 8 + jr) * 128);
    const uint32_t aSel = (uint32_t)(t8 >> 1);
    const uint32_t bRow = (uint32_t)((wn * 64 + (t8 >> 1) * 8 + jr) * 128);
    const uint32_t bSel = (uint32_t)(t8 & 1);
    const uint32_t jrx  = (uint32_t)jr;

    uint32_t acc[8][8][2];   // fp16x2 accumulators
    #pragma unroll
    for (int mt = 0; mt < 8; ++mt)
        #pragma unroll
        for (int nt = 0; nt < 8; ++nt) { acc[mt][nt][0] = 0u; acc[mt][nt][1] = 0u; }

    // prologue: stage 0 into buffer 0
    load_stage(smb, 0, bm, bn, 0, tid);
    asm volatile("cp.async.commit_group;" ::: "memory");

    #pragma unroll
    for (int s = 0; s < 4; ++s) {
        asm volatile("cp.async.wait_group 0;" ::: "memory");
        __syncthreads();
        if (s < 3) {
            load_stage(smb, ((s + 1) & 1) * BUF_BYTES, bm, bn, s + 1, tid);
            asm volatile("cp.async.commit_group;" ::: "memory");
        }

        const uint32_t bufA = smb + (s & 1) * BUF_BYTES + aRow;
        const uint32_t bufB = smb + (s & 1) * BUF_BYTES + 32768 + bRow;

        #pragma unroll
        for (int ks = 0; ks < 4; ++ks) {   // k16 steps within K=64 stage
            const uint32_t aOff = ((((uint32_t)(2 * ks) | aSel) ^ jrx) << 4);
            const uint32_t bOff = ((((uint32_t)(2 * ks) | bSel) ^ jrx) << 4);

            uint32_t afr[8][4], bfr[4][4];
            #pragma unroll
            for (int mt = 0; mt < 8; ++mt) ldsm4(afr[mt], bufA + mt * 2048 + aOff);
            #pragma unroll
            for (int bt = 0; bt < 4; ++bt) ldsm4(bfr[bt], bufB + bt * 2048 + bOff);

            #pragma unroll
            for (int mt = 0; mt < 8; ++mt)
                #pragma unroll
                for (int bt = 0; bt < 4; ++bt) {
                    mma_f16acc(acc[mt][2 * bt],     afr[mt], bfr[bt]);
                    mma_f16acc(acc[mt][2 * bt + 1], afr[mt], bfr[bt] + 2);
                }
        }
    }

    // ---- epilogue: pure argmax (B pre-scaled), lane reduce, global atomicMax ----
    #pragma unroll
    for (int mt = 0; mt < 8; ++mt) {
        #pragma unroll
        for (int half = 0; half < 2; ++half) {
            float bestv = -3.402823e38f;
            int   bcol  = 0;
            #pragma unroll
            for (int nt = 0; nt < 8; ++nt) {
                int    c0 = wn * 64 + nt * 8 + 2 * tig;
                float2 f  = __half22float2(*(__half2*)&acc[mt][nt][half]);
                if (f.x > bestv) { bestv = f.x; bcol = c0; }
                if (f.y > bestv) { bestv = f.y; bcol = c0 + 1; }
            }
            unsigned u = __float_as_uint(bestv);
            u = (u & 0x80000000u) ? ~u : (u | 0x80000000u);
            unsigned q = (unsigned)(bn + bcol);
            unsigned long long key =
                ((unsigned long long)u << 32) | (unsigned long long)(0xFFFFFFFFu - q);

            unsigned long long o = __shfl_xor_sync(0xFFFFFFFFu, key, 1);
            if (o > key) key = o;
            o = __shfl_xor_sync(0xFFFFFFFFu, key, 2);
            if (o > key) key = o;

            if (tig == 0) {
                int row = bm + wm * 128 + mt * 16 + g + half * 8;
                atomicMax(&g_best[row], key);
            }
        }
    }

    // signal this tile done for the overlapped k_loss
    __threadfence();
    __syncthreads();
    if (tid == 0) atomicAdd(&g_done[blockIdx.x], 1u);
}

// ---------------- kernel 2: gather dot (B pre-scaled), exact cosine, fixed-point sum ----------------
__global__ void k_loss(float* __restrict__ out) {
    const int tid = threadIdx.x;          // 256
    const int grp = tid >> 3;             // 0..31 : pixel slot
    const int l8  = tid & 7;
    const int p   = blockIdx.x * 32 + grp;

    // wait until all 128 GEMM tiles covering this bm-group finished
    if (tid == 0) {
        while (((volatile unsigned int*)g_done)[blockIdx.x >> 3] < 128u) __nanosleep(64);
        __threadfence();
    }
    __syncthreads();

    unsigned long long key = g_best[p];
    int q = (int)(0xFFFFFFFFu - (unsigned)(key & 0xFFFFFFFFull));

    const __half* ap = g_ah + (size_t)p * CCH + l8 * 32;
    const __half* bp = g_bh + (size_t)q * CCH + l8 * 32;
    float dot = 0.f;
    #pragma unroll
    for (int i = 0; i < 4; ++i) {
        uint4 av = *(const uint4*)(ap + i * 8);
        uint4 bv = *(const uint4*)(bp + i * 8);
        const __half2* ah2 = (const __half2*)&av;
        const __half2* bh2 = (const __half2*)&bv;
        #pragma unroll
        for (int j = 0; j < 4; ++j) {
            float2 af = __half22float2(ah2[j]);
            float2 bf = __half22float2(bh2[j]);
            dot = fmaf(af.x, bf.x, dot);
            dot = fmaf(af.y, bf.y, dot);
        }
    }
    dot += __shfl_xor_sync(0xFFFFFFFFu, dot, 1);
    dot += __shfl_xor_sync(0xFFFFFFFFu, dot, 2);
    dot += __shfl_xor_sync(0xFFFFFFFFu, dot, 4);

    // reset g_best for the next graph replay (reads above are long retired)
    if (l8 == 0) g_best[p] = 0ULL;

    __shared__ float sred[32];
    if (l8 == 0) {
        // dot is a . (b * inv_nb[q]) -> true dot = dot / inv_nb[q]
        float cs = dot / (g_inv_nb[q] * (g_an[p] + EPSF) * (g_bn[q] + EPSF));
        sred[grp] = 1.f - cs;
    }
    __syncthreads();
    if (tid < 32) {
        float v = sred[tid];
        #pragma unroll
        for (int m = 16; m >= 1; m >>= 1)
            v += __shfl_xor_sync(0xFFFFFFFFu, v, m);
        if (tid == 0) {
            unsigned long long fx = (unsigned long long)((double)v * 4294967296.0);
            atomicAdd(&g_sum, fx);
            __threadfence();
            unsigned int done = atomicAdd(&g_cnt, 1u);
            if (done == gridDim.x - 1) {
                // unique last block: every spin in this call has passed
                __threadfence();
                unsigned long long s = atomicAdd(&g_sum, 0ULL);
                out[0] = (float)((double)s * (1.0 / 4294967296.0) / (double)HW);
                g_sum = 0ULL;
                g_cnt = 0u;
                for (int i = 0; i < 1024; ++i) g_flag[i] = 0u;
                for (int i = 0; i < 64; ++i)  g_done[i] = 0u;
            }
        }
    }
}

// ---------------- launch ----------------
extern "C" void kernel_launch(void* const* d_in, const int* in_sizes, int n_in,
                              void* d_out, int out_size) {
    const float* a = (const float*)d_in[0];
    const float* b = (const float*)d_in[1];
    float* out = (float*)d_out;

    cudaFuncSetAttribute(k_gemm, cudaFuncAttributeMaxDynamicSharedMemorySize, SMEM_BYTES);

    k_cvt<<<dim3(HW / 32, 2), dim3(32, 8)>>>(a, b);

    cudaLaunchAttribute attr;
    attr.id = cudaLaunchAttributeProgrammaticStreamSerialization;
    attr.val.programmaticStreamSerializationAllowed = 1;

    cudaLaunchConfig_t cfg = {};
    cfg.gridDim  = dim3(HW / 256, HW / 128);
    cfg.blockDim = dim3(128);
    cfg.dynamicSmemBytes = SMEM_BYTES;
    cfg.stream   = 0;
    cfg.attrs    = &attr;
    cfg.numAttrs = 1;
    cudaLaunchKernelEx(&cfg, k_gemm);

    cudaLaunchConfig_t cfg2 = {};
    cfg2.gridDim  = dim3(HW / 32);
    cfg2.blockDim = dim3(256);
    cfg2.stream   = 0;
    cfg2.attrs    = &attr;
    cfg2.numAttrs = 1;
    cudaLaunchKernelEx(&cfg2, k_loss, out);
}

// round 16
// speedup vs baseline: 1.1387x; 1.1387x over previous
#include <cuda_runtime.h>
#include <cuda_fp16.h>
#include <cstdint>

#define HW   16384
#define CCH  256
#define EPSF 1e-8f

// ---------------- scratch (no allocations allowed) ----------------
__device__ float              g_inv_nb[HW];
__device__ float              g_bn[HW];
__device__ float              g_an[HW];
__device__ unsigned long long g_best[HW];
__device__ unsigned long long g_sum;
__device__ unsigned int       g_cnt;
__device__ __half             g_ah[HW * CCH];      // fp16 a, [p][c] K-major, 8MB
__device__ __half             g_bh[HW * CCH];      // fp16 b * inv_nb[q], [q][c], 8MB

// ---------------- helpers ----------------
__device__ __forceinline__ uint32_t smem_to_u32(const void* p) {
    uint32_t a;
    asm("{ .reg .u64 t; cvta.to.shared.u64 t, %1; cvt.u32.u64 %0, t; }" : "=r"(a) : "l"(p));
    return a;
}
// .cg: bypass L1 (stage data is never re-read through L1; avoids pollution)
__device__ __forceinline__ void cp16(uint32_t dst, const void* src) {
    asm volatile("cp.async.cg.shared.global [%0], [%1], 16;" :: "r"(dst), "l"(src) : "memory");
}
__device__ __forceinline__ void mma_f16acc(uint32_t* d, const uint32_t* a, const uint32_t* b) {
    asm volatile(
        "mma.sync.aligned.m16n8k16.row.col.f16.f16.f16.f16 "
        "{%0,%1}, {%2,%3,%4,%5}, {%6,%7}, {%0,%1};"
        : "+r"(d[0]), "+r"(d[1])
        : "r"(a[0]), "r"(a[1]), "r"(a[2]), "r"(a[3]), "r"(b[0]), "r"(b[1]));
}
__device__ __forceinline__ void ldsm4(uint32_t* r, uint32_t addr) {
    asm volatile("ldmatrix.sync.aligned.m8n8.x4.shared.b16 {%0,%1,%2,%3}, [%4];"
                 : "=r"(r[0]), "=r"(r[1]), "=r"(r[2]), "=r"(r[3]) : "r"(addr));
}

// smem: 2 stage buffers of (A 32KB + B 16KB), K=64 stages, 128B rows
static constexpr int BUF_BYTES  = 49152;
static constexpr int SMEM_BYTES = 2 * BUF_BYTES;   // 98304

// ---------------- kernel 0: fused transpose->fp16 + exact norms + init ----------------
// b is stored PRE-SCALED by inv_nb so the GEMM epilogue is a pure argmax.
__global__ void k_cvt(const float* __restrict__ a, const float* __restrict__ b) {
    __shared__ float t[32][257];   // [pixel][channel]
    __shared__ float ps[8][33];
    __shared__ float scl[32];
    const int z = blockIdx.y;
    const float* src = z ? b : a;
    __half*      dst = z ? g_bh : g_ah;
    const int p0 = blockIdx.x * 32;
    const int tx = threadIdx.x, ty = threadIdx.y;   // 32 x 8

    if (z == 0 && blockIdx.x == 0 && tx == 0 && ty == 0) { g_sum = 0ULL; g_cnt = 0u; }

    float ss = 0.f;
    #pragma unroll
    for (int i = 0; i < 32; ++i) {
        int c = ty + i * 8;
        float v = src[(size_t)c * HW + p0 + tx];
        t[tx][c] = v;
        ss = fmaf(v, v, ss);
    }
    ps[ty][tx] = ss;
    __syncthreads();

    if (ty == 0) {
        float s = 0.f;
        #pragma unroll
        for (int j = 0; j < 8; ++j) s += ps[j][tx];
        int p = p0 + tx;
        if (z) {
            float inv = 1.f / (sqrtf(s + EPSF) + EPSF);
            g_inv_nb[p] = inv;
            g_bn[p]     = sqrtf(s);
            g_best[p]   = 0ULL;
            scl[tx]     = inv;
        } else {
            g_an[p] = sqrtf(s);
            scl[tx] = 1.f;
        }
    }
    __syncthreads();

    #pragma unroll
    for (int pp = 0; pp < 4; ++pp) {
        int px = ty * 4 + pp;
        int c0 = tx * 8;
        float sc = scl[px];
        uint32_t w[4];
        #pragma unroll
        for (int j = 0; j < 4; ++j) {
            __half2 h = __floats2half2_rn(t[px][c0 + 2 * j] * sc, t[px][c0 + 2 * j + 1] * sc);
            w[j] = *(uint32_t*)&h;
        }
        *(uint4*)(dst + (size_t)(p0 + px) * CCH + c0) = make_uint4(w[0], w[1], w[2], w[3]);
    }
}

// ---------------- kernel 1: fp16 GEMM, CTA 256x128, warp tile 128x64, fp16 acc ----------------
__device__ __forceinline__ void load_stage(uint32_t smb, int bufOff,
                                           int bm, int bn, int s, int tid) {
    // A: 256 rows x 64 K fp16 (128B rows), 2048 16B-chunks
    #pragma unroll
    for (int i = 0; i < 16; ++i) {
        int idx = tid + i * 128;
        int row = idx >> 3, seg = idx & 7;
        uint32_t d = smb + bufOff + row * 128 + ((seg ^ (row & 7)) << 4);
        cp16(d, g_ah + (size_t)(bm + row) * CCH + s * 64 + seg * 8);
    }
    // B: 128 rows x 64 K fp16, 1024 chunks
    #pragma unroll
    for (int i = 0; i < 8; ++i) {
        int idx = tid + i * 128;
        int row = idx >> 3, seg = idx & 7;
        uint32_t d = smb + bufOff + 32768 + row * 128 + ((seg ^ (row & 7)) << 4);
        cp16(d, g_bh + (size_t)(bn + row) * CCH + s * 64 + seg * 8);
    }
}

__global__ void __launch_bounds__(128, 2)
k_gemm() {
    extern __shared__ __align__(1024) char sm[];
    const uint32_t smb = smem_to_u32(sm);
    const int tid  = threadIdx.x;
    const int lane = tid & 31;
    const int wid  = tid >> 5;    // 0..3
    const int wm   = wid & 1;     // 2 warps along M (128 rows each)
    const int wn   = wid >> 1;    // 2 warps along N (64 cols each)
    const int g    = lane >> 2;
    const int tig  = lane & 3;
    const int t8   = lane >> 3;
    const int jr   = lane & 7;

    const int bm = blockIdx.x * 256;   // M fast
    const int bn = blockIdx.y * 128;

    // ldmatrix per-lane address invariants
    const uint32_t aRow = (uint32_t)((wm * 128 + (t8 & 1) * 8 + jr) * 128);
    const uint32_t aSel = (uint32_t)(t8 >> 1);
    const uint32_t bRow = (uint32_t)((wn * 64 + (t8 >> 1) * 8 + jr) * 128);
    const uint32_t bSel = (uint32_t)(t8 & 1);
    const uint32_t jrx  = (uint32_t)jr;

    uint32_t acc[8][8][2];   // fp16x2 accumulators
    #pragma unroll
    for (int mt = 0; mt < 8; ++mt)
        #pragma unroll
        for (int nt = 0; nt < 8; ++nt) { acc[mt][nt][0] = 0u; acc[mt][nt][1] = 0u; }

    // prologue: stage 0 into buffer 0
    load_stage(smb, 0, bm, bn, 0, tid);
    asm volatile("cp.async.commit_group;" ::: "memory");

    #pragma unroll
    for (int s = 0; s < 4; ++s) {
        asm volatile("cp.async.wait_group 0;" ::: "memory");
        __syncthreads();
        if (s < 3) {
            load_stage(smb, ((s + 1) & 1) * BUF_BYTES, bm, bn, s + 1, tid);
            asm volatile("cp.async.commit_group;" ::: "memory");
        }

        const uint32_t bufA = smb + (s & 1) * BUF_BYTES + aRow;
        const uint32_t bufB = smb + (s & 1) * BUF_BYTES + 32768 + bRow;

        #pragma unroll
        for (int ks = 0; ks < 4; ++ks) {   // k16 steps within K=64 stage
            const uint32_t aOff = ((((uint32_t)(2 * ks) | aSel) ^ jrx) << 4);
            const uint32_t bOff = ((((uint32_t)(2 * ks) | bSel) ^ jrx) << 4);

            uint32_t afr[8][4], bfr[4][4];
            #pragma unroll
            for (int mt = 0; mt < 8; ++mt) ldsm4(afr[mt], bufA + mt * 2048 + aOff);
            #pragma unroll
            for (int bt = 0; bt < 4; ++bt) ldsm4(bfr[bt], bufB + bt * 2048 + bOff);

            #pragma unroll
            for (int mt = 0; mt < 8; ++mt)
                #pragma unroll
                for (int bt = 0; bt < 4; ++bt) {
                    mma_f16acc(acc[mt][2 * bt],     afr[mt], bfr[bt]);
                    mma_f16acc(acc[mt][2 * bt + 1], afr[mt], bfr[bt] + 2);
                }
        }
    }

    // ---- epilogue: pure argmax (B pre-scaled), lane reduce, global atomicMax ----
    #pragma unroll
    for (int mt = 0; mt < 8; ++mt) {
        #pragma unroll
        for (int half = 0; half < 2; ++half) {
            float bestv = -3.402823e38f;
            int   bcol  = 0;
            #pragma unroll
            for (int nt = 0; nt < 8; ++nt) {
                int    c0 = wn * 64 + nt * 8 + 2 * tig;
                float2 f  = __half22float2(*(__half2*)&acc[mt][nt][half]);
                if (f.x > bestv) { bestv = f.x; bcol = c0; }
                if (f.y > bestv) { bestv = f.y; bcol = c0 + 1; }
            }
            unsigned u = __float_as_uint(bestv);
            u = (u & 0x80000000u) ? ~u : (u | 0x80000000u);
            unsigned q = (unsigned)(bn + bcol);
            unsigned long long key =
                ((unsigned long long)u << 32) | (unsigned long long)(0xFFFFFFFFu - q);

            unsigned long long o = __shfl_xor_sync(0xFFFFFFFFu, key, 1);
            if (o > key) key = o;
            o = __shfl_xor_sync(0xFFFFFFFFu, key, 2);
            if (o > key) key = o;

            if (tig == 0) {
                int row = bm + wm * 128 + mt * 16 + g + half * 8;
                atomicMax(&g_best[row], key);
            }
        }
    }
}

// ---------------- kernel 2: gather dot (16 lanes/pixel), exact cosine, fixed-point sum ----------------
__global__ void k_loss(float* __restrict__ out) {
    const int tid = threadIdx.x;          // 256
    const int grp = tid >> 4;             // 0..15 : pixel slot
    const int l16 = tid & 15;
    const int p   = blockIdx.x * 16 + grp;

    unsigned long long key = g_best[p];
    int q = (int)(0xFFFFFFFFu - (unsigned)(key & 0xFFFFFFFFull));

    const __half* ap = g_ah + (size_t)p * CCH + l16 * 16;
    const __half* bp = g_bh + (size_t)q * CCH + l16 * 16;
    float dot = 0.f;
    #pragma unroll
    for (int i = 0; i < 2; ++i) {
        uint4 av = *(const uint4*)(ap + i * 8);
        uint4 bv = *(const uint4*)(bp + i * 8);
        const __half2* ah2 = (const __half2*)&av;
        const __half2* bh2 = (const __half2*)&bv;
        #pragma unroll
        for (int j = 0; j < 4; ++j) {
            float2 af = __half22float2(ah2[j]);
            float2 bf = __half22float2(bh2[j]);
            dot = fmaf(af.x, bf.x, dot);
            dot = fmaf(af.y, bf.y, dot);
        }
    }
    dot += __shfl_xor_sync(0xFFFFFFFFu, dot, 1);
    dot += __shfl_xor_sync(0xFFFFFFFFu, dot, 2);
    dot += __shfl_xor_sync(0xFFFFFFFFu, dot, 4);
    dot += __shfl_xor_sync(0xFFFFFFFFu, dot, 8);

    __shared__ float sred[16];
    if (l16 == 0) {
        // dot is a . (b * inv_nb[q]) -> true dot = dot / inv_nb[q]
        float cs = dot / (g_inv_nb[q] * (g_an[p] + EPSF) * (g_bn[q] + EPSF));
        sred[grp] = 1.f - cs;
    }
    __syncthreads();
    if (tid < 16) {
        float v = sred[tid];
        #pragma unroll
        for (int m = 8; m >= 1; m >>= 1)
            v += __shfl_xor_sync(0x0000FFFFu, v, m);
        if (tid == 0) {
            unsigned long long fx = (unsigned long long)((double)v * 4294967296.0);
            atomicAdd(&g_sum, fx);
            __threadfence();
            unsigned int done = atomicAdd(&g_cnt, 1u);
            if (done == gridDim.x - 1) {
                __threadfence();
                unsigned long long s = atomicAdd(&g_sum, 0ULL);
                out[0] = (float)((double)s * (1.0 / 4294967296.0) / (double)HW);
            }
        }
    }
}

// ---------------- launch ----------------
extern "C" void kernel_launch(void* const* d_in, const int* in_sizes, int n_in,
                              void* d_out, int out_size) {
    const float* a = (const float*)d_in[0];
    const float* b = (const float*)d_in[1];
    float* out = (float*)d_out;

    cudaFuncSetAttribute(k_gemm, cudaFuncAttributeMaxDynamicSharedMemorySize, SMEM_BYTES);

    k_cvt<<<dim3(HW / 32, 2), dim3(32, 8)>>>(a, b);
    k_gemm<<<dim3(HW / 256, HW / 128), 128, SMEM_BYTES>>>();
    k_loss<<<HW / 16, 256>>>(out);
}